// round 6
// baseline (speedup 1.0000x reference)
#include <cuda_runtime.h>
#include <cuda_bf16.h>
#include <math.h>

// Problem constants
#define IMGS 48
#define H 512
#define W 512
#define IMG_ELEMS (H * W)
#define VALID 506
#define N_TOTAL (48.0 * 512.0 * 512.0)
#define N_SSIM  (48.0 * 506.0 * 506.0)

// k_ssim tile: 64x32 outputs, halo 70x38 rows.
#define TW 64
#define TH 32
#define HH 38
#define P4 65           // hs4 pitch (float4 units)
#define P1 66           // hs1 pitch (floats, even -> float2-aligned stores)
#define GRID_X 8
#define GRID_Y 16
#define NBLK (GRID_X * GRID_Y * IMGS)    // 6144
#define RB 32           // range blocks per image

// smem layout (floats): hs4[38][65] float4, hs1[38][66] float, scr[32]
#define HS4_F (HH * P4 * 4)              // 9880
#define HS1_F (HH * P1)                  // 2508
#define SMEM_FLOATS (HS4_F + HS1_F + 32) // 12420 -> 48.5 KB

// Device scratch
__device__ float g_pabs[NBLK];
__device__ float g_psq[NBLK];
__device__ float g_pS[NBLK];
__device__ float g_pmin[IMGS * RB];
__device__ float g_pmax[IMGS * RB];

// ---------------------------------------------------------------------------
// Kernel 1: per-image min/max of y_true*mask. 32 blocks/img x 256 thr x 8 f4.
// ---------------------------------------------------------------------------
__global__ void __launch_bounds__(256) k_range(
    const float4* __restrict__ t4, const float4* __restrict__ m4)
{
    int img = blockIdx.x >> 5;
    int blk = blockIdx.x & 31;
    long base = (long)img * (IMG_ELEMS / 4) + (long)blk * 2048;

    float mn = INFINITY, mx = -INFINITY;
#pragma unroll
    for (int i = 0; i < 8; i++) {
        long idx = base + threadIdx.x + i * 256;
        float4 t = t4[idx];
        float4 m = m4[idx];
        float y0 = t.x * m.x, y1 = t.y * m.y, y2 = t.z * m.z, y3 = t.w * m.w;
        mn = fminf(mn, fminf(fminf(y0, y1), fminf(y2, y3)));
        mx = fmaxf(mx, fmaxf(fmaxf(y0, y1), fmaxf(y2, y3)));
    }
#pragma unroll
    for (int o = 16; o; o >>= 1) {
        mn = fminf(mn, __shfl_down_sync(0xffffffffu, mn, o));
        mx = fmaxf(mx, __shfl_down_sync(0xffffffffu, mx, o));
    }
    __shared__ float wmn[8], wmx[8];
    int lane = threadIdx.x & 31, w = threadIdx.x >> 5;
    if (lane == 0) { wmn[w] = mn; wmx[w] = mx; }
    __syncthreads();
    if (threadIdx.x == 0) {
        float MN = INFINITY, MX = -INFINITY;
#pragma unroll
        for (int i = 0; i < 8; i++) {
            MN = fminf(MN, wmn[i]);
            MX = fmaxf(MX, wmx[i]);
        }
        g_pmin[blockIdx.x] = MN;
        g_pmax[blockIdx.x] = MX;
    }
}

// ---------------------------------------------------------------------------
// Kernel 2: fused SSIM + MAE/MSE.
// Load phase computes 7-tap horizontal sums IN REGISTERS via warp shuffles
// and writes only the h-sum planes to smem (no pixel tile, no h-pass phase).
//
// Per halo row (one warp): lane L holds pixel pair (2L, 2L+1); all lanes also
// load ext pair 32+(L&3) (pixels 64..71, replicated).  For each of the 5
// quantities q in {x, y, xx, yy, xy}:
//   P(L)   = q(2L) + q(2L+1)
//   S3(L)  = P(L) + P(L+1) + P(L+2)
//   h(2L)  = S3(L) + q0(L+3)          (pixels 2L .. 2L+6)
//   h(2L+1)= q1(L) + S3(L+1)          (pixels 2L+1 .. 2L+7)
// where indices >= 32 select the ext-pair variants (shfl idx wraps mod 32).
// ---------------------------------------------------------------------------
__global__ void __launch_bounds__(256) k_ssim(
    const float* __restrict__ P_, const float* __restrict__ T_,
    const float* __restrict__ M_)
{
    extern __shared__ float sm[];
    float4* hs4 = (float4*)sm;               // [38][65] : (s0,s1,s2,s3)
    float*  hs1 = sm + HS4_F;                // [38][66] : s4
    float*  scr = sm + HS4_F + HS1_F;

    int img = blockIdx.z;
    int ox0 = blockIdx.x * TW;
    int oy0 = blockIdx.y * TH;
    int tid = threadIdx.x;
    int lane = tid & 31;
    int warp = tid >> 5;
    const unsigned F = 0xffffffffu;

    // ---- C1/C2 from 32 range partials (warp 0) ----
    if (warp == 0) {
        float mn = g_pmin[img * RB + lane];
        float mx = g_pmax[img * RB + lane];
#pragma unroll
        for (int o = 16; o; o >>= 1) {
            mn = fminf(mn, __shfl_down_sync(F, mn, o));
            mx = fmaxf(mx, __shfl_down_sync(F, mx, o));
        }
        if (lane == 0) {
            float d = mx - mn;
            float c1 = 0.01f * d, c2 = 0.03f * d;
            scr[24] = c1 * c1;
            scr[25] = c2 * c2;
        }
    }

    const float* Pi = P_ + (size_t)img * IMG_ELEMS;
    const float* Ti = T_ + (size_t)img * IMG_ELEMS;
    const float* Mi = M_ + (size_t)img * IMG_ELEMS;

    // ---- Fused halo load + horizontal pass + MAE/MSE ----
    float sa = 0.f, sq = 0.f;
    {
        int cmain = ox0 + 2 * lane;                         // always <= 510
        int cext = min(ox0 + 64 + 2 * (lane & 3), W - 2);   // clamped
        bool u1 = lane < 31, u2 = lane < 30, u3 = lane < 29;

#pragma unroll
        for (int it = 0; it < 5; it++) {
            int r = warp + it * 8;
            if (it == 4 && r >= HH) continue;
            int gy = min(oy0 + r, H - 1);
            const float2* Pr = (const float2*)(Pi + gy * W);
            const float2* Tr = (const float2*)(Ti + gy * W);
            const float2* Mr = (const float2*)(Mi + gy * W);

            float2 p = Pr[cmain >> 1];
            float2 t = Tr[cmain >> 1];
            float2 m = Mr[cmain >> 1];
            float2 pe = Pr[cext >> 1];
            float2 te = Tr[cext >> 1];
            float2 me = Mr[cext >> 1];

            float x0 = p.x * m.x, y0 = t.x * m.x;
            float x1 = p.y * m.y, y1 = t.y * m.y;
            float xe0 = pe.x * me.x, ye0 = te.x * me.x;
            float xe1 = pe.y * me.y, ye1 = te.y * me.y;

            if (it < 4) {                      // owned 64x32 region exactly
                float d0 = x0 - y0, d1 = x1 - y1;
                sa += fabsf(d0) + fabsf(d1);
                sq += d0 * d0 + d1 * d1;
            }

            float q0[5] = { x0, y0, x0 * x0, y0 * y0, x0 * y0 };
            float q1[5] = { x1, y1, x1 * x1, y1 * y1, x1 * y1 };
            float q0e[5] = { xe0, ye0, xe0 * xe0, ye0 * ye0, xe0 * ye0 };
            float q1e[5] = { xe1, ye1, xe1 * xe1, ye1 * ye1, xe1 * ye1 };

            float hv[5], ho[5];
#pragma unroll
            for (int q = 0; q < 5; q++) {
                float Pp = q0[q] + q1[q];
                float Pe = q0e[q] + q1e[q];
                float a1 = __shfl_sync(F, Pp, lane + 1);
                float b1 = __shfl_sync(F, Pe, lane + 1);
                float Pd1 = u1 ? a1 : b1;
                float a2 = __shfl_sync(F, Pp, lane + 2);
                float b2 = __shfl_sync(F, Pe, lane + 2);
                float Pd2 = u2 ? a2 : b2;
                float S3 = Pp + Pd1 + Pd2;
                float S3e = Pe + __shfl_down_sync(F, Pe, 1)
                               + __shfl_down_sync(F, Pe, 2);
                float aq = __shfl_sync(F, q0[q], lane + 3);
                float bq = __shfl_sync(F, q0e[q], lane + 3);
                hv[q] = S3 + (u3 ? aq : bq);
                float as = __shfl_sync(F, S3, lane + 1);
                float bs = __shfl_sync(F, S3e, lane + 1);
                ho[q] = q1[q] + (u1 ? as : bs);
            }

            float4* o4 = hs4 + r * P4 + 2 * lane;
            o4[0] = make_float4(hv[0], hv[1], hv[2], hv[3]);
            o4[1] = make_float4(ho[0], ho[1], ho[2], ho[3]);
            *(float2*)(hs1 + r * P1 + 2 * lane) = make_float2(hv[4], ho[4]);
        }
    }
    __syncthreads();

    // ---- Vertical pass: thread (tx, ty) -> col tx, rows ty*8..ty*8+7 ----
    int tx = tid & 63;
    int ty = tid >> 6;
    int r0 = ty * 8;

    float C1 = scr[24], C2 = scr[25];
    float4 b4[7]; float b1[7];
    float t0 = 0.f, t1 = 0.f, t2 = 0.f, t3 = 0.f, t4 = 0.f;
    b4[6] = make_float4(0.f, 0.f, 0.f, 0.f); b1[6] = 0.f;
#pragma unroll
    for (int j = 0; j < 6; j++) {
        float4 v = hs4[(r0 + j) * P4 + tx];
        float  u = hs1[(r0 + j) * P1 + tx];
        b4[j] = v; b1[j] = u;
        t0 += v.x; t1 += v.y; t2 += v.z; t3 += v.w; t4 += u;
    }

    const float inv = 1.f / 49.f;
    const float cov = 49.f / 48.f;
    float lsum = 0.f;
    int gox = ox0 + tx;

#pragma unroll
    for (int i = 0; i < 8; i++) {
        int slot = (6 + i) % 7;
        float4 v = hs4[(r0 + 6 + i) * P4 + tx];
        float  u = hs1[(r0 + 6 + i) * P1 + tx];
        t0 += v.x - b4[slot].x;
        t1 += v.y - b4[slot].y;
        t2 += v.z - b4[slot].z;
        t3 += v.w - b4[slot].w;
        t4 += u - b1[slot];
        b4[slot] = v; b1[slot] = u;
        int goy = oy0 + r0 + i;
        if (gox < VALID && goy < VALID) {
            float ux = t0 * inv, uy = t1 * inv;
            float vx  = cov * (t2 * inv - ux * ux);
            float vy  = cov * (t3 * inv - uy * uy);
            float vxy = cov * (t4 * inv - ux * uy);
            float A1 = 2.f * ux * uy + C1;
            float A2 = 2.f * vxy + C2;
            float B1 = ux * ux + uy * uy + C1;
            float B2 = vx + vy + C2;
            lsum += __fdividef(A1 * A2, B1 * B2);
        }
    }

    // ---- Block reduce (sa, sq, lsum) -> partial stores ----
#pragma unroll
    for (int o = 16; o; o >>= 1) {
        sa += __shfl_down_sync(F, sa, o);
        sq += __shfl_down_sync(F, sq, o);
        lsum += __shfl_down_sync(F, lsum, o);
    }
    __syncthreads();
    if (lane == 0) { scr[warp] = sa; scr[8 + warp] = sq; scr[16 + warp] = lsum; }
    __syncthreads();
    if (tid == 0) {
        float A = 0.f, Q = 0.f, S = 0.f;
#pragma unroll
        for (int i = 0; i < 8; i++) { A += scr[i]; Q += scr[8 + i]; S += scr[16 + i]; }
        int bid = blockIdx.x + (blockIdx.y << 3) + (blockIdx.z << 7);
        g_pabs[bid] = A;
        g_psq[bid] = Q;
        g_pS[bid] = S;
    }
}

// ---------------------------------------------------------------------------
// Kernel 3: final reduction of 6144 partials (double) -> 4 outputs
// ---------------------------------------------------------------------------
__global__ void __launch_bounds__(256) k_final(float* __restrict__ out) {
    int tid = threadIdx.x;
    double a = 0.0, q = 0.0, s = 0.0;
    for (int i = tid; i < NBLK; i += 256) {
        a += (double)g_pabs[i];
        q += (double)g_psq[i];
        s += (double)g_pS[i];
    }
#pragma unroll
    for (int o = 16; o; o >>= 1) {
        a += __shfl_down_sync(0xffffffffu, a, o);
        q += __shfl_down_sync(0xffffffffu, q, o);
        s += __shfl_down_sync(0xffffffffu, s, o);
    }
    __shared__ double wa[8], wq[8], ws[8];
    int lane = tid & 31, w = tid >> 5;
    if (lane == 0) { wa[w] = a; wq[w] = q; ws[w] = s; }
    __syncthreads();
    if (tid == 0) {
        double A = 0.0, Q = 0.0, S = 0.0;
#pragma unroll
        for (int i = 0; i < 8; i++) { A += wa[i]; Q += wq[i]; S += ws[i]; }
        double mae = A / N_TOTAL;
        double mse = Q / N_TOTAL;
        double ssim_loss = 1.0 - S / N_SSIM;
        double total = mae + 0.5 * mse + 0.2 * ssim_loss;
        out[0] = (float)total;
        out[1] = (float)mae;
        out[2] = (float)mse;
        out[3] = (float)ssim_loss;
    }
}

// ---------------------------------------------------------------------------
extern "C" void kernel_launch(void* const* d_in, const int* in_sizes, int n_in,
                              void* d_out, int out_size)
{
    const float* y_pred = (const float*)d_in[0];
    const float* y_true = (const float*)d_in[1];
    const float* mask   = (const float*)d_in[2];
    float* out = (float*)d_out;

    cudaFuncSetAttribute(k_ssim, cudaFuncAttributeMaxDynamicSharedMemorySize,
                         SMEM_FLOATS * 4);

    k_range<<<IMGS * RB, 256>>>((const float4*)y_true, (const float4*)mask);
    dim3 grid(GRID_X, GRID_Y, IMGS);
    k_ssim<<<grid, 256, SMEM_FLOATS * 4>>>(y_pred, y_true, mask);
    k_final<<<1, 256>>>(out);
}

// round 8
// speedup vs baseline: 1.3043x; 1.3043x over previous
#include <cuda_runtime.h>
#include <cuda_bf16.h>
#include <math.h>

// Problem constants
#define IMGS 48
#define H 512
#define W 512
#define IMG_ELEMS (H * W)
#define VALID 506
#define N_TOTAL (48.0 * 512.0 * 512.0)
#define N_SSIM  (48.0 * 506.0 * 506.0)

// k_ssim tile: 64x32 outputs, halo 70x38 (72 cols as 36 float2 pairs).
#define TW 64
#define TH 32
#define HH 38
#define PSXY 37         // sxy pitch in float4; 37%8=5, gcd(5,8)=1 -> conflict-free
#define P4H 33          // hs4 half pitch (float4), 32 cols + 1 pad
#define P1H 33          // hs1 half pitch (float)
#define GRID_X 8
#define GRID_Y 16
#define NBLK (GRID_X * GRID_Y * IMGS)    // 6144
#define RB 32           // range blocks per image

// smem (floats): sxy[38][37]f4 + hs4[38][33]f4 + hs1[38][33] + scr + dred
#define SXY_F (HH * PSXY * 4)            // 5624
#define HS4_F (HH * P4H * 4)             // 5016
#define HS1_F (HH * P1H)                 // 1254
#define SCR_OFF (SXY_F + HS4_F + HS1_F)  // 11894
#define SMEM_FLOATS (SCR_OFF + 32 + 48)  // + 24 doubles for final reduce

// Device scratch
__device__ float g_pabs[NBLK];
__device__ float g_psq[NBLK];
__device__ float g_pS[NBLK];
__device__ float g_pmin[IMGS * RB];
__device__ float g_pmax[IMGS * RB];
__device__ unsigned g_count;             // zero-init; self-resets each call

// ---------------------------------------------------------------------------
// Kernel 1: per-image min/max of y_true*mask. 32 blocks/img x 256 thr x 8 f4.
// ---------------------------------------------------------------------------
__global__ void __launch_bounds__(256) k_range(
    const float4* __restrict__ t4, const float4* __restrict__ m4)
{
    int img = blockIdx.x >> 5;
    int blk = blockIdx.x & 31;
    long base = (long)img * (IMG_ELEMS / 4) + (long)blk * 2048;

    float mn = INFINITY, mx = -INFINITY;
#pragma unroll
    for (int i = 0; i < 8; i++) {
        long idx = base + threadIdx.x + i * 256;
        float4 t = t4[idx];
        float4 m = m4[idx];
        float y0 = t.x * m.x, y1 = t.y * m.y, y2 = t.z * m.z, y3 = t.w * m.w;
        mn = fminf(mn, fminf(fminf(y0, y1), fminf(y2, y3)));
        mx = fmaxf(mx, fmaxf(fmaxf(y0, y1), fmaxf(y2, y3)));
    }
#pragma unroll
    for (int o = 16; o; o >>= 1) {
        mn = fminf(mn, __shfl_down_sync(0xffffffffu, mn, o));
        mx = fmaxf(mx, __shfl_down_sync(0xffffffffu, mx, o));
    }
    __shared__ float wmn[8], wmx[8];
    int lane = threadIdx.x & 31, w = threadIdx.x >> 5;
    if (lane == 0) { wmn[w] = mn; wmx[w] = mx; }
    __syncthreads();
    if (threadIdx.x == 0) {
        float MN = INFINITY, MX = -INFINITY;
#pragma unroll
        for (int i = 0; i < 8; i++) {
            MN = fminf(MN, wmn[i]);
            MX = fmaxf(MX, wmx[i]);
        }
        g_pmin[blockIdx.x] = MN;
        g_pmax[blockIdx.x] = MX;
    }
}

// ---------------------------------------------------------------------------
// Kernel 2: fused SSIM + MAE/MSE + final reduction (last block).
// Round-5 load phase (batched high-MLP). h/v passes in two 32-col halves
// sharing one hs buffer -> 47.9 KB smem -> 4 blocks/SM.
// ---------------------------------------------------------------------------
__global__ void __launch_bounds__(256, 4) k_ssim(
    const float* __restrict__ P_, const float* __restrict__ T_,
    const float* __restrict__ M_, float* __restrict__ out)
{
    extern __shared__ float sm[];
    float4* sxy = (float4*)sm;                   // [38][37] (x0,y0,x1,y1)
    float4* hs4 = (float4*)(sm + SXY_F);         // [38][33] (s0,s1,s2,s3)
    float*  hs1 = sm + SXY_F + HS4_F;            // [38][33] s4
    float*  scr = sm + SCR_OFF;                  // 32 floats
    double* dred = (double*)(sm + SCR_OFF + 32); // 24 doubles (final reduce)

    int img = blockIdx.z;
    int ox0 = blockIdx.x * TW;
    int oy0 = blockIdx.y * TH;
    int tid = threadIdx.x;
    int lane = tid & 31;
    int warp = tid >> 5;
    const unsigned F = 0xffffffffu;

    // ---- C1/C2 from 32 range partials (warp 0) ----
    if (warp == 0) {
        float mn = g_pmin[img * RB + lane];
        float mx = g_pmax[img * RB + lane];
#pragma unroll
        for (int o = 16; o; o >>= 1) {
            mn = fminf(mn, __shfl_down_sync(F, mn, o));
            mx = fmaxf(mx, __shfl_down_sync(F, mx, o));
        }
        if (lane == 0) {
            float d = mx - mn;
            float c1 = 0.01f * d, c2 = 0.03f * d;
            scr[24] = c1 * c1;
            scr[25] = c2 * c2;
        }
    }

    const float* Pi = P_ + (size_t)img * IMG_ELEMS;
    const float* Ti = T_ + (size_t)img * IMG_ELEMS;
    const float* Mi = M_ + (size_t)img * IMG_ELEMS;

    // ---- Halo load (round-5, batched) + MAE/MSE on owned region ----
    float sa = 0.f, sq = 0.f;
    {
        int cmain = min(ox0 + 2 * lane, W - 2);
        bool has_e = lane < 4;
        int cext = min(ox0 + 64 + 2 * (lane & 3), W - 2);

#pragma unroll
        for (int it = 0; it < 5; it++) {
            int r = warp + it * 8;
            if (it == 4 && r >= HH) continue;
            int gy = min(oy0 + r, H - 1);
            const float2* Pr = (const float2*)(Pi + gy * W);
            const float2* Tr = (const float2*)(Ti + gy * W);
            const float2* Mr = (const float2*)(Mi + gy * W);

            float2 p = Pr[cmain >> 1];
            float2 t = Tr[cmain >> 1];
            float2 m = Mr[cmain >> 1];
            float x0 = p.x * m.x, y0 = t.x * m.x;
            float x1 = p.y * m.y, y1 = t.y * m.y;
            sxy[r * PSXY + lane] = make_float4(x0, y0, x1, y1);
            if (it < 4) {
                float d0 = x0 - y0, d1 = x1 - y1;
                sa += fabsf(d0) + fabsf(d1);
                sq += d0 * d0 + d1 * d1;
            }
            if (has_e) {
                float2 pe = Pr[cext >> 1];
                float2 te = Tr[cext >> 1];
                float2 me = Mr[cext >> 1];
                sxy[r * PSXY + 32 + (lane & 3)] = make_float4(
                    pe.x * me.x, te.x * me.x, pe.y * me.y, te.y * me.y);
            }
        }
    }
    __syncthreads();

    float C1 = scr[24], C2 = scr[25];
    const float inv = 1.f / 49.f;
    const float cov = 49.f / 48.f;
    float lsum = 0.f;

#pragma unroll 1
    for (int half = 0; half < 2; half++) {
        // ---- h-pass for 32 cols: tasks (g 0..3, r 0..37) = 152 threads ----
        if (tid < 152) {
            int g = tid / 38;
            int r = tid - g * 38;
            const float4* row = sxy + r * PSXY + half * 16 + g * 4;
            float4 wv[7];
#pragma unroll
            for (int j = 0; j < 7; j++) wv[j] = row[j];

#define PX(p) ((p & 1) ? wv[(p) >> 1].z : wv[(p) >> 1].x)
#define PY(p) ((p & 1) ? wv[(p) >> 1].w : wv[(p) >> 1].y)
            float s0 = 0.f, s1 = 0.f, s2 = 0.f, s3 = 0.f, s4 = 0.f;
#pragma unroll
            for (int j = 0; j < 7; j++) {
                float x = PX(j), y = PY(j);
                s0 += x; s1 += y; s2 += x * x; s3 += y * y; s4 += x * y;
            }
            float4* o4 = hs4 + r * P4H + g * 8;
            float*  o1 = hs1 + r * P1H + g * 8;
            o4[0] = make_float4(s0, s1, s2, s3);
            o1[0] = s4;
#pragma unroll
            for (int j = 1; j < 8; j++) {
                float xa = PX(6 + j), ya = PY(6 + j);
                float xd = PX(j - 1), yd = PY(j - 1);
                s0 += xa - xd;
                s1 += ya - yd;
                s2 += xa * xa - xd * xd;
                s3 += ya * ya - yd * yd;
                s4 += xa * ya - xd * yd;
                o4[j] = make_float4(s0, s1, s2, s3);
                o1[j] = s4;
            }
#undef PX
#undef PY
        }
        __syncthreads();

        // ---- v-pass: tx = local col (32), ty (8) -> rows ty*4..ty*4+3 ----
        {
            int tx = tid & 31;
            int ty = tid >> 5;
            int r0 = ty * 4;

            float4 b4[7]; float b1[7];
            float t0 = 0.f, t1 = 0.f, t2 = 0.f, t3 = 0.f, t4 = 0.f;
            b4[6] = make_float4(0.f, 0.f, 0.f, 0.f); b1[6] = 0.f;
#pragma unroll
            for (int j = 0; j < 6; j++) {
                float4 v = hs4[(r0 + j) * P4H + tx];
                float  u = hs1[(r0 + j) * P1H + tx];
                b4[j] = v; b1[j] = u;
                t0 += v.x; t1 += v.y; t2 += v.z; t3 += v.w; t4 += u;
            }
            int gox = ox0 + half * 32 + tx;
#pragma unroll
            for (int i = 0; i < 4; i++) {
                int slot = (6 + i) % 7;
                float4 v = hs4[(r0 + 6 + i) * P4H + tx];
                float  u = hs1[(r0 + 6 + i) * P1H + tx];
                t0 += v.x - b4[slot].x;
                t1 += v.y - b4[slot].y;
                t2 += v.z - b4[slot].z;
                t3 += v.w - b4[slot].w;
                t4 += u - b1[slot];
                b4[slot] = v; b1[slot] = u;
                int goy = oy0 + r0 + i;
                if (gox < VALID && goy < VALID) {
                    float ux = t0 * inv, uy = t1 * inv;
                    float vx  = cov * (t2 * inv - ux * ux);
                    float vy  = cov * (t3 * inv - uy * uy);
                    float vxy = cov * (t4 * inv - ux * uy);
                    float A1 = 2.f * ux * uy + C1;
                    float A2 = 2.f * vxy + C2;
                    float B1 = ux * ux + uy * uy + C1;
                    float B2 = vx + vy + C2;
                    lsum += __fdividef(A1 * A2, B1 * B2);
                }
            }
        }
        __syncthreads();   // before next half overwrites hs
    }

    // ---- Block reduce (sa, sq, lsum) -> partial stores ----
#pragma unroll
    for (int o = 16; o; o >>= 1) {
        sa += __shfl_down_sync(F, sa, o);
        sq += __shfl_down_sync(F, sq, o);
        lsum += __shfl_down_sync(F, lsum, o);
    }
    if (lane == 0) { scr[warp] = sa; scr[8 + warp] = sq; scr[16 + warp] = lsum; }
    __syncthreads();
    __shared__ bool is_last;
    if (tid == 0) {
        float A = 0.f, Q = 0.f, S = 0.f;
#pragma unroll
        for (int i = 0; i < 8; i++) { A += scr[i]; Q += scr[8 + i]; S += scr[16 + i]; }
        int bid = blockIdx.x + (blockIdx.y << 3) + (blockIdx.z << 7);
        g_pabs[bid] = A;
        g_psq[bid] = Q;
        g_pS[bid] = S;
        __threadfence();
        unsigned old = atomicAdd(&g_count, 1u);
        is_last = (old == NBLK - 1);
    }
    __syncthreads();

    // ---- Last block: reduce all partials, write outputs, reset counter ----
    if (is_last) {
        double a = 0.0, q = 0.0, s = 0.0;
        for (int i = tid; i < NBLK; i += 256) {
            a += (double)g_pabs[i];
            q += (double)g_psq[i];
            s += (double)g_pS[i];
        }
#pragma unroll
        for (int o = 16; o; o >>= 1) {
            a += __shfl_down_sync(F, a, o);
            q += __shfl_down_sync(F, q, o);
            s += __shfl_down_sync(F, s, o);
        }
        if (lane == 0) { dred[warp] = a; dred[8 + warp] = q; dred[16 + warp] = s; }
        __syncthreads();
        if (tid == 0) {
            double A = 0.0, Q = 0.0, S = 0.0;
#pragma unroll
            for (int i = 0; i < 8; i++) {
                A += dred[i]; Q += dred[8 + i]; S += dred[16 + i];
            }
            double mae = A / N_TOTAL;
            double mse = Q / N_TOTAL;
            double ssim_loss = 1.0 - S / N_SSIM;
            double total = mae + 0.5 * mse + 0.2 * ssim_loss;
            out[0] = (float)total;
            out[1] = (float)mae;
            out[2] = (float)mse;
            out[3] = (float)ssim_loss;
            g_count = 0;                 // reset for next graph replay
        }
    }
}

// ---------------------------------------------------------------------------
extern "C" void kernel_launch(void* const* d_in, const int* in_sizes, int n_in,
                              void* d_out, int out_size)
{
    const float* y_pred = (const float*)d_in[0];
    const float* y_true = (const float*)d_in[1];
    const float* mask   = (const float*)d_in[2];
    float* out = (float*)d_out;

    cudaFuncSetAttribute(k_ssim, cudaFuncAttributeMaxDynamicSharedMemorySize,
                         SMEM_FLOATS * 4);

    k_range<<<IMGS * RB, 256>>>((const float4*)y_true, (const float4*)mask);
    dim3 grid(GRID_X, GRID_Y, IMGS);
    k_ssim<<<grid, 256, SMEM_FLOATS * 4>>>(y_pred, y_true, mask, out);
}

// round 9
// speedup vs baseline: 1.3574x; 1.0407x over previous
#include <cuda_runtime.h>
#include <cuda_bf16.h>
#include <cuda_fp16.h>
#include <math.h>

// Problem constants
#define IMGS 48
#define H 512
#define W 512
#define IMG_ELEMS (H * W)
#define VALID 506
#define N_TOTAL (48.0 * 512.0 * 512.0)
#define N_SSIM  (48.0 * 506.0 * 506.0)

// k_ssim tile: 64x32 outputs, halo 70x38 (72 cols as 36 float2 pairs).
#define TW 64
#define TH 32
#define HH 38
#define PSXY 37          // sxy pitch in float4; conflict-free
#define GRID_X 8
#define GRID_Y 16
#define NBLK (GRID_X * GRID_Y * IMGS)    // 6144
#define RB 64            // range blocks per image

// smem byte layout
#define SXY_BYTES (HH * PSXY * 16)       // 22496
#define HSA_OFF  SXY_BYTES               // half2[38][36] rows of 144B
#define HSROW    144
#define HSB_OFF  (HSA_OFF + HH * HSROW)  // 27968
#define HS1_OFF  (HSB_OFF + HH * HSROW)  // 33440, half[38][40] rows of 80B
#define HS1ROW   80
#define SCR_OFF  (HS1_OFF + HH * HS1ROW) // 36480 (32 floats)
#define DRED_OFF (SCR_OFF + 128)         // 36608 (24 doubles)
#define SMEM_BYTES (DRED_OFF + 192)      // 36800

// Device scratch
__device__ float g_pabs[NBLK];
__device__ float g_psq[NBLK];
__device__ float g_pS[NBLK];
__device__ float g_pmin[IMGS * RB];
__device__ float g_pmax[IMGS * RB];
__device__ unsigned g_count;             // zero-init; self-resets each call

__device__ __forceinline__ unsigned pack2(float a, float b) {
    __half2 h = __floats2half2_rn(a, b);
    return *reinterpret_cast<unsigned*>(&h);
}

// ---------------------------------------------------------------------------
// Kernel 1: per-image min/max of y_true*mask. 64 blocks/img x 256 thr x 4 f4.
// ---------------------------------------------------------------------------
__global__ void __launch_bounds__(256) k_range(
    const float4* __restrict__ t4, const float4* __restrict__ m4)
{
    int img = blockIdx.x >> 6;
    int blk = blockIdx.x & 63;
    long base = (long)img * (IMG_ELEMS / 4) + (long)blk * 1024;

    float mn = INFINITY, mx = -INFINITY;
#pragma unroll
    for (int i = 0; i < 4; i++) {
        long idx = base + threadIdx.x + i * 256;
        float4 t = t4[idx];
        float4 m = m4[idx];
        float y0 = t.x * m.x, y1 = t.y * m.y, y2 = t.z * m.z, y3 = t.w * m.w;
        mn = fminf(mn, fminf(fminf(y0, y1), fminf(y2, y3)));
        mx = fmaxf(mx, fmaxf(fmaxf(y0, y1), fmaxf(y2, y3)));
    }
#pragma unroll
    for (int o = 16; o; o >>= 1) {
        mn = fminf(mn, __shfl_down_sync(0xffffffffu, mn, o));
        mx = fmaxf(mx, __shfl_down_sync(0xffffffffu, mx, o));
    }
    __shared__ float wmn[8], wmx[8];
    int lane = threadIdx.x & 31, w = threadIdx.x >> 5;
    if (lane == 0) { wmn[w] = mn; wmx[w] = mx; }
    __syncthreads();
    if (threadIdx.x == 0) {
        float MN = INFINITY, MX = -INFINITY;
#pragma unroll
        for (int i = 0; i < 8; i++) {
            MN = fminf(MN, wmn[i]);
            MX = fmaxf(MX, wmx[i]);
        }
        g_pmin[blockIdx.x] = MN;
        g_pmax[blockIdx.x] = MX;
    }
}

// ---------------------------------------------------------------------------
// Kernel 2: fused SSIM + MAE/MSE + final reduction (last block).
// hs planes stored as fp16: hsA=(s0,s1) half2, hsB=(s2,s3) half2, hs1=s4 half.
// Halves L1 wavefronts in v-pass loads and h-pass stores.
// ---------------------------------------------------------------------------
__global__ void __launch_bounds__(256, 4) k_ssim(
    const float* __restrict__ P_, const float* __restrict__ T_,
    const float* __restrict__ M_, float* __restrict__ out)
{
    extern __shared__ char smc[];
    float4* sxy = (float4*)smc;                  // [38][37] (x0,y0,x1,y1)
    char*   hsA = smc + HSA_OFF;
    char*   hsB = smc + HSB_OFF;
    char*   hs1 = smc + HS1_OFF;
    float*  scr = (float*)(smc + SCR_OFF);       // 32 floats
    double* dred = (double*)(smc + DRED_OFF);    // 24 doubles

    int img = blockIdx.z;
    int ox0 = blockIdx.x * TW;
    int oy0 = blockIdx.y * TH;
    int tid = threadIdx.x;
    int lane = tid & 31;
    int warp = tid >> 5;
    const unsigned F = 0xffffffffu;

    // ---- C1/C2 from 64 range partials (warp 0, 2 per lane) ----
    if (warp == 0) {
        float mn = fminf(g_pmin[img * RB + lane], g_pmin[img * RB + 32 + lane]);
        float mx = fmaxf(g_pmax[img * RB + lane], g_pmax[img * RB + 32 + lane]);
#pragma unroll
        for (int o = 16; o; o >>= 1) {
            mn = fminf(mn, __shfl_down_sync(F, mn, o));
            mx = fmaxf(mx, __shfl_down_sync(F, mx, o));
        }
        if (lane == 0) {
            float d = mx - mn;
            float c1 = 0.01f * d, c2 = 0.03f * d;
            scr[24] = c1 * c1;
            scr[25] = c2 * c2;
        }
    }

    const float* Pi = P_ + (size_t)img * IMG_ELEMS;
    const float* Ti = T_ + (size_t)img * IMG_ELEMS;
    const float* Mi = M_ + (size_t)img * IMG_ELEMS;

    // ---- Halo load (batched high-MLP) + MAE/MSE on owned region ----
    float sa = 0.f, sq = 0.f;
    {
        int cmain = min(ox0 + 2 * lane, W - 2);
        bool has_e = lane < 4;
        int cext = min(ox0 + 64 + 2 * (lane & 3), W - 2);

#pragma unroll
        for (int it = 0; it < 5; it++) {
            int r = warp + it * 8;
            if (it == 4 && r >= HH) continue;
            int gy = min(oy0 + r, H - 1);
            const float2* Pr = (const float2*)(Pi + gy * W);
            const float2* Tr = (const float2*)(Ti + gy * W);
            const float2* Mr = (const float2*)(Mi + gy * W);

            float2 p = Pr[cmain >> 1];
            float2 t = Tr[cmain >> 1];
            float2 m = Mr[cmain >> 1];
            float x0 = p.x * m.x, y0 = t.x * m.x;
            float x1 = p.y * m.y, y1 = t.y * m.y;
            sxy[r * PSXY + lane] = make_float4(x0, y0, x1, y1);
            if (it < 4) {
                float d0 = x0 - y0, d1 = x1 - y1;
                sa += fabsf(d0) + fabsf(d1);
                sq += d0 * d0 + d1 * d1;
            }
            if (has_e) {
                float2 pe = Pr[cext >> 1];
                float2 te = Tr[cext >> 1];
                float2 me = Mr[cext >> 1];
                sxy[r * PSXY + 32 + (lane & 3)] = make_float4(
                    pe.x * me.x, te.x * me.x, pe.y * me.y, te.y * me.y);
            }
        }
    }
    __syncthreads();

    float C1 = scr[24], C2 = scr[25];
    const float inv = 1.f / 49.f;
    const float cov = 49.f / 48.f;
    float lsum = 0.f;

#pragma unroll 1
    for (int half = 0; half < 2; half++) {
        // ---- h-pass for 32 cols: tasks (g 0..3, r 0..37) = 152 threads ----
        if (tid < 152) {
            int g = tid / 38;
            int r = tid - g * 38;
            const float4* row = sxy + r * PSXY + half * 16 + g * 4;
            float4 wv[7];
#pragma unroll
            for (int j = 0; j < 7; j++) wv[j] = row[j];

#define PX(p) ((p & 1) ? wv[(p) >> 1].z : wv[(p) >> 1].x)
#define PY(p) ((p & 1) ? wv[(p) >> 1].w : wv[(p) >> 1].y)
            float s0 = 0.f, s1 = 0.f, s2 = 0.f, s3 = 0.f, s4 = 0.f;
#pragma unroll
            for (int j = 0; j < 7; j++) {
                float x = PX(j), y = PY(j);
                s0 += x; s1 += y; s2 += x * x; s3 += y * y; s4 += x * y;
            }
            unsigned pa[8], pb[8];
            float s4v[8];
            pa[0] = pack2(s0, s1); pb[0] = pack2(s2, s3); s4v[0] = s4;
#pragma unroll
            for (int j = 1; j < 8; j++) {
                float xa = PX(6 + j), ya = PY(6 + j);
                float xd = PX(j - 1), yd = PY(j - 1);
                s0 += xa - xd;
                s1 += ya - yd;
                s2 += xa * xa - xd * xd;
                s3 += ya * ya - yd * yd;
                s4 += xa * ya - xd * yd;
                pa[j] = pack2(s0, s1);
                pb[j] = pack2(s2, s3);
                s4v[j] = s4;
            }
#undef PX
#undef PY
            // Packed stores: 2x uint4 per plane A/B, 1x uint4 for s4 plane.
            uint4* oA = (uint4*)(hsA + r * HSROW + g * 32);
            uint4* oB = (uint4*)(hsB + r * HSROW + g * 32);
            oA[0] = make_uint4(pa[0], pa[1], pa[2], pa[3]);
            oA[1] = make_uint4(pa[4], pa[5], pa[6], pa[7]);
            oB[0] = make_uint4(pb[0], pb[1], pb[2], pb[3]);
            oB[1] = make_uint4(pb[4], pb[5], pb[6], pb[7]);
            uint4* o1 = (uint4*)(hs1 + r * HS1ROW + g * 16);
            o1[0] = make_uint4(pack2(s4v[0], s4v[1]), pack2(s4v[2], s4v[3]),
                               pack2(s4v[4], s4v[5]), pack2(s4v[6], s4v[7]));
        }
        __syncthreads();

        // ---- v-pass: tx = local col (32), ty (8) -> rows ty*4..ty*4+3 ----
        {
            int tx = tid & 31;
            int ty = tid >> 5;
            int r0 = ty * 4;

            float b0[7], b1v[7], b2[7], b3[7], b4v[7];
            float t0 = 0.f, t1 = 0.f, t2 = 0.f, t3 = 0.f, t4 = 0.f;
            b0[6] = b1v[6] = b2[6] = b3[6] = b4v[6] = 0.f;
#pragma unroll
            for (int j = 0; j < 6; j++) {
                int r = r0 + j;
                __half2 ha = *(const __half2*)(hsA + r * HSROW + tx * 4);
                __half2 hb = *(const __half2*)(hsB + r * HSROW + tx * 4);
                __half  hu = *(const __half*)(hs1 + r * HS1ROW + tx * 2);
                float2 fa = __half22float2(ha);
                float2 fb = __half22float2(hb);
                float fu = __half2float(hu);
                b0[j] = fa.x; b1v[j] = fa.y; b2[j] = fb.x; b3[j] = fb.y; b4v[j] = fu;
                t0 += fa.x; t1 += fa.y; t2 += fb.x; t3 += fb.y; t4 += fu;
            }
            int gox = ox0 + half * 32 + tx;
#pragma unroll
            for (int i = 0; i < 4; i++) {
                int slot = (6 + i) % 7;
                int r = r0 + 6 + i;
                __half2 ha = *(const __half2*)(hsA + r * HSROW + tx * 4);
                __half2 hb = *(const __half2*)(hsB + r * HSROW + tx * 4);
                __half  hu = *(const __half*)(hs1 + r * HS1ROW + tx * 2);
                float2 fa = __half22float2(ha);
                float2 fb = __half22float2(hb);
                float fu = __half2float(hu);
                t0 += fa.x - b0[slot];
                t1 += fa.y - b1v[slot];
                t2 += fb.x - b2[slot];
                t3 += fb.y - b3[slot];
                t4 += fu - b4v[slot];
                b0[slot] = fa.x; b1v[slot] = fa.y;
                b2[slot] = fb.x; b3[slot] = fb.y; b4v[slot] = fu;
                int goy = oy0 + r0 + i;
                if (gox < VALID && goy < VALID) {
                    float ux = t0 * inv, uy = t1 * inv;
                    float vx  = cov * (t2 * inv - ux * ux);
                    float vy  = cov * (t3 * inv - uy * uy);
                    float vxy = cov * (t4 * inv - ux * uy);
                    float A1 = 2.f * ux * uy + C1;
                    float A2 = 2.f * vxy + C2;
                    float B1 = ux * ux + uy * uy + C1;
                    float B2 = vx + vy + C2;
                    lsum += __fdividef(A1 * A2, B1 * B2);
                }
            }
        }
        __syncthreads();   // before next half overwrites hs
    }

    // ---- Block reduce (sa, sq, lsum) -> partial stores ----
#pragma unroll
    for (int o = 16; o; o >>= 1) {
        sa += __shfl_down_sync(F, sa, o);
        sq += __shfl_down_sync(F, sq, o);
        lsum += __shfl_down_sync(F, lsum, o);
    }
    if (lane == 0) { scr[warp] = sa; scr[8 + warp] = sq; scr[16 + warp] = lsum; }
    __syncthreads();
    __shared__ bool is_last;
    if (tid == 0) {
        float A = 0.f, Q = 0.f, S = 0.f;
#pragma unroll
        for (int i = 0; i < 8; i++) { A += scr[i]; Q += scr[8 + i]; S += scr[16 + i]; }
        int bid = blockIdx.x + (blockIdx.y << 3) + (blockIdx.z << 7);
        g_pabs[bid] = A;
        g_psq[bid] = Q;
        g_pS[bid] = S;
        __threadfence();
        unsigned old = atomicAdd(&g_count, 1u);
        is_last = (old == NBLK - 1);
    }
    __syncthreads();

    // ---- Last block: reduce all partials, write outputs, reset counter ----
    if (is_last) {
        double a = 0.0, q = 0.0, s = 0.0;
        for (int i = tid; i < NBLK; i += 256) {
            a += (double)g_pabs[i];
            q += (double)g_psq[i];
            s += (double)g_pS[i];
        }
#pragma unroll
        for (int o = 16; o; o >>= 1) {
            a += __shfl_down_sync(F, a, o);
            q += __shfl_down_sync(F, q, o);
            s += __shfl_down_sync(F, s, o);
        }
        if (lane == 0) { dred[warp] = a; dred[8 + warp] = q; dred[16 + warp] = s; }
        __syncthreads();
        if (tid == 0) {
            double A = 0.0, Q = 0.0, S = 0.0;
#pragma unroll
            for (int i = 0; i < 8; i++) {
                A += dred[i]; Q += dred[8 + i]; S += dred[16 + i];
            }
            double mae = A / N_TOTAL;
            double mse = Q / N_TOTAL;
            double ssim_loss = 1.0 - S / N_SSIM;
            double total = mae + 0.5 * mse + 0.2 * ssim_loss;
            out[0] = (float)total;
            out[1] = (float)mae;
            out[2] = (float)mse;
            out[3] = (float)ssim_loss;
            g_count = 0;                 // reset for next graph replay
        }
    }
}

// ---------------------------------------------------------------------------
extern "C" void kernel_launch(void* const* d_in, const int* in_sizes, int n_in,
                              void* d_out, int out_size)
{
    const float* y_pred = (const float*)d_in[0];
    const float* y_true = (const float*)d_in[1];
    const float* mask   = (const float*)d_in[2];
    float* out = (float*)d_out;

    cudaFuncSetAttribute(k_ssim, cudaFuncAttributeMaxDynamicSharedMemorySize,
                         SMEM_BYTES);

    k_range<<<IMGS * RB, 256>>>((const float4*)y_true, (const float4*)mask);
    dim3 grid(GRID_X, GRID_Y, IMGS);
    k_ssim<<<grid, 256, SMEM_BYTES>>>(y_pred, y_true, mask, out);
}

// round 11
// speedup vs baseline: 1.3636x; 1.0046x over previous
#include <cuda_runtime.h>
#include <cuda_bf16.h>
#include <cuda_fp16.h>
#include <math.h>

// Problem constants
#define IMGS 48
#define H 512
#define W 512
#define IMG_ELEMS (H * W)
#define VALID 506
#define N_TOTAL (48.0 * 512.0 * 512.0)
#define N_SSIM  (48.0 * 506.0 * 506.0)

// k_ssim tile: 64x32 outputs, halo 70x38 (72 cols as 36 float2 pairs).
#define TW 64
#define TH 32
#define HH 38
#define PSXY 37          // sxy pitch in float4; conflict-free
#define GRID_X 8
#define GRID_Y 16
#define NBLK (GRID_X * GRID_Y * IMGS)    // 6144
#define RB 64            // range blocks per image

// smem byte layout (full-width fp16 hs planes; ALL rows 16B-aligned)
#define SXY_BYTES (HH * PSXY * 16)       // 22496
#define HSA_OFF  SXY_BYTES               // half2[38][64], row 272B
#define HSROW    272
#define HSB_OFF  (HSA_OFF + HH * HSROW)  // 32832
#define HS1_OFF  (HSB_OFF + HH * HSROW)  // 43168, half[38][72], row 144B (16B mult!)
#define HS1ROW   144
#define SCR_OFF  (HS1_OFF + HH * HS1ROW) // 48640 (32 floats)
#define DRED_OFF (SCR_OFF + 128)         // 48768 (24 doubles, 8B-aligned)
#define SMEM_BYTES (DRED_OFF + 192)      // 48960 (~47.8 KB)

// Device scratch
__device__ float g_pabs[NBLK];
__device__ float g_psq[NBLK];
__device__ float g_pS[NBLK];
__device__ float g_pmin[IMGS * RB];
__device__ float g_pmax[IMGS * RB];
__device__ unsigned g_count;             // zero-init; self-resets each call

__device__ __forceinline__ unsigned pack2(float a, float b) {
    __half2 h = __floats2half2_rn(a, b);
    return *reinterpret_cast<unsigned*>(&h);
}

// ---------------------------------------------------------------------------
// Kernel 1: per-image min/max of y_true*mask. 64 blocks/img x 256 thr x 4 f4.
// ---------------------------------------------------------------------------
__global__ void __launch_bounds__(256) k_range(
    const float4* __restrict__ t4, const float4* __restrict__ m4)
{
    int img = blockIdx.x >> 6;
    int blk = blockIdx.x & 63;
    long base = (long)img * (IMG_ELEMS / 4) + (long)blk * 1024;

    float mn = INFINITY, mx = -INFINITY;
#pragma unroll
    for (int i = 0; i < 4; i++) {
        long idx = base + threadIdx.x + i * 256;
        float4 t = t4[idx];
        float4 m = m4[idx];
        float y0 = t.x * m.x, y1 = t.y * m.y, y2 = t.z * m.z, y3 = t.w * m.w;
        mn = fminf(mn, fminf(fminf(y0, y1), fminf(y2, y3)));
        mx = fmaxf(mx, fmaxf(fmaxf(y0, y1), fmaxf(y2, y3)));
    }
#pragma unroll
    for (int o = 16; o; o >>= 1) {
        mn = fminf(mn, __shfl_down_sync(0xffffffffu, mn, o));
        mx = fmaxf(mx, __shfl_down_sync(0xffffffffu, mx, o));
    }
    __shared__ float wmn[8], wmx[8];
    int lane = threadIdx.x & 31, w = threadIdx.x >> 5;
    if (lane == 0) { wmn[w] = mn; wmx[w] = mx; }
    __syncthreads();
    if (threadIdx.x == 0) {
        float MN = INFINITY, MX = -INFINITY;
#pragma unroll
        for (int i = 0; i < 8; i++) {
            MN = fminf(MN, wmn[i]);
            MX = fmaxf(MX, wmx[i]);
        }
        g_pmin[blockIdx.x] = MN;
        g_pmax[blockIdx.x] = MX;
    }
}

// ---------------------------------------------------------------------------
// Kernel 2: fused SSIM + MAE/MSE + final reduction (last block).
// Full-width fp16 hs planes; single h-pass; v-pass 8 rows/thread.
// ---------------------------------------------------------------------------
__global__ void __launch_bounds__(256, 4) k_ssim(
    const float* __restrict__ P_, const float* __restrict__ T_,
    const float* __restrict__ M_, float* __restrict__ out)
{
    extern __shared__ char smc[];
    float4* sxy = (float4*)smc;                  // [38][37] (x0,y0,x1,y1)
    char*   hsA = smc + HSA_OFF;
    char*   hsB = smc + HSB_OFF;
    char*   hs1 = smc + HS1_OFF;
    float*  scr = (float*)(smc + SCR_OFF);       // 32 floats
    double* dred = (double*)(smc + DRED_OFF);    // 24 doubles

    int img = blockIdx.z;
    int ox0 = blockIdx.x * TW;
    int oy0 = blockIdx.y * TH;
    int tid = threadIdx.x;
    int lane = tid & 31;
    int warp = tid >> 5;
    const unsigned F = 0xffffffffu;

    // ---- C1/C2 from 64 range partials (warp 0, 2 per lane) ----
    if (warp == 0) {
        float mn = fminf(g_pmin[img * RB + lane], g_pmin[img * RB + 32 + lane]);
        float mx = fmaxf(g_pmax[img * RB + lane], g_pmax[img * RB + 32 + lane]);
#pragma unroll
        for (int o = 16; o; o >>= 1) {
            mn = fminf(mn, __shfl_down_sync(F, mn, o));
            mx = fmaxf(mx, __shfl_down_sync(F, mx, o));
        }
        if (lane == 0) {
            float d = mx - mn;
            float c1 = 0.01f * d, c2 = 0.03f * d;
            scr[24] = c1 * c1;
            scr[25] = c2 * c2;
        }
    }

    const float* Pi = P_ + (size_t)img * IMG_ELEMS;
    const float* Ti = T_ + (size_t)img * IMG_ELEMS;
    const float* Mi = M_ + (size_t)img * IMG_ELEMS;

    // ---- Halo load (batched high-MLP) + MAE/MSE on owned region ----
    float sa = 0.f, sq = 0.f;
    {
        int cmain = min(ox0 + 2 * lane, W - 2);
        bool has_e = lane < 4;
        int cext = min(ox0 + 64 + 2 * (lane & 3), W - 2);

#pragma unroll
        for (int it = 0; it < 5; it++) {
            int r = warp + it * 8;
            if (it == 4 && r >= HH) continue;
            int gy = min(oy0 + r, H - 1);
            const float2* Pr = (const float2*)(Pi + gy * W);
            const float2* Tr = (const float2*)(Ti + gy * W);
            const float2* Mr = (const float2*)(Mi + gy * W);

            float2 p = Pr[cmain >> 1];
            float2 t = Tr[cmain >> 1];
            float2 m = Mr[cmain >> 1];
            float x0 = p.x * m.x, y0 = t.x * m.x;
            float x1 = p.y * m.y, y1 = t.y * m.y;
            sxy[r * PSXY + lane] = make_float4(x0, y0, x1, y1);
            if (it < 4) {
                float d0 = x0 - y0, d1 = x1 - y1;
                sa += fabsf(d0) + fabsf(d1);
                sq += d0 * d0 + d1 * d1;
            }
            if (has_e) {
                float2 pe = Pr[cext >> 1];
                float2 te = Tr[cext >> 1];
                float2 me = Mr[cext >> 1];
                sxy[r * PSXY + 32 + (lane & 3)] = make_float4(
                    pe.x * me.x, te.x * me.x, pe.y * me.y, te.y * me.y);
            }
        }
    }
    __syncthreads();

    float C1 = scr[24], C2 = scr[25];
    const float inv = 1.f / 49.f;
    const float cov = 49.f / 48.f;
    float lsum = 0.f;

    // ---- Single h-pass: 304 tasks (chunk g 0..7 x row r 0..37) ----
#pragma unroll 1
    for (int l = tid; l < 8 * HH; l += 256) {
        int g = l / HH;
        int r = l - g * HH;
        const float4* row = sxy + r * PSXY + g * 4;
        float4 wv[7];
#pragma unroll
        for (int j = 0; j < 7; j++) wv[j] = row[j];

#define PX(p) ((p & 1) ? wv[(p) >> 1].z : wv[(p) >> 1].x)
#define PY(p) ((p & 1) ? wv[(p) >> 1].w : wv[(p) >> 1].y)
        float s0 = 0.f, s1 = 0.f, s2 = 0.f, s3 = 0.f, s4 = 0.f;
#pragma unroll
        for (int j = 0; j < 7; j++) {
            float x = PX(j), y = PY(j);
            s0 += x; s1 += y; s2 += x * x; s3 += y * y; s4 += x * y;
        }
        unsigned pa[8], pb[8];
        float s4v[8];
        pa[0] = pack2(s0, s1); pb[0] = pack2(s2, s3); s4v[0] = s4;
#pragma unroll
        for (int j = 1; j < 8; j++) {
            float xa = PX(6 + j), ya = PY(6 + j);
            float xd = PX(j - 1), yd = PY(j - 1);
            s0 += xa - xd;
            s1 += ya - yd;
            s2 += xa * xa - xd * xd;
            s3 += ya * ya - yd * yd;
            s4 += xa * ya - xd * yd;
            pa[j] = pack2(s0, s1);
            pb[j] = pack2(s2, s3);
            s4v[j] = s4;
        }
#undef PX
#undef PY
        uint4* oA = (uint4*)(hsA + r * HSROW + g * 32);
        uint4* oB = (uint4*)(hsB + r * HSROW + g * 32);
        oA[0] = make_uint4(pa[0], pa[1], pa[2], pa[3]);
        oA[1] = make_uint4(pa[4], pa[5], pa[6], pa[7]);
        oB[0] = make_uint4(pb[0], pb[1], pb[2], pb[3]);
        oB[1] = make_uint4(pb[4], pb[5], pb[6], pb[7]);
        uint4* o1 = (uint4*)(hs1 + r * HS1ROW + g * 16);
        o1[0] = make_uint4(pack2(s4v[0], s4v[1]), pack2(s4v[2], s4v[3]),
                           pack2(s4v[4], s4v[5]), pack2(s4v[6], s4v[7]));
    }
    __syncthreads();

    // ---- v-pass: tx = col (64), ty (4) -> rows ty*8..ty*8+7 ----
    {
        int tx = tid & 63;
        int ty = tid >> 6;
        int r0 = ty * 8;

        float b0[7], b1v[7], b2[7], b3[7], b4v[7];
        float t0 = 0.f, t1 = 0.f, t2 = 0.f, t3 = 0.f, t4 = 0.f;
        b0[6] = b1v[6] = b2[6] = b3[6] = b4v[6] = 0.f;
#pragma unroll
        for (int j = 0; j < 6; j++) {
            int r = r0 + j;
            float2 fa = __half22float2(*(const __half2*)(hsA + r * HSROW + tx * 4));
            float2 fb = __half22float2(*(const __half2*)(hsB + r * HSROW + tx * 4));
            float fu = __half2float(*(const __half*)(hs1 + r * HS1ROW + tx * 2));
            b0[j] = fa.x; b1v[j] = fa.y; b2[j] = fb.x; b3[j] = fb.y; b4v[j] = fu;
            t0 += fa.x; t1 += fa.y; t2 += fb.x; t3 += fb.y; t4 += fu;
        }
        int gox = ox0 + tx;
#pragma unroll
        for (int i = 0; i < 8; i++) {
            int slot = (6 + i) % 7;
            int r = r0 + 6 + i;
            float2 fa = __half22float2(*(const __half2*)(hsA + r * HSROW + tx * 4));
            float2 fb = __half22float2(*(const __half2*)(hsB + r * HSROW + tx * 4));
            float fu = __half2float(*(const __half*)(hs1 + r * HS1ROW + tx * 2));
            t0 += fa.x - b0[slot];
            t1 += fa.y - b1v[slot];
            t2 += fb.x - b2[slot];
            t3 += fb.y - b3[slot];
            t4 += fu - b4v[slot];
            b0[slot] = fa.x; b1v[slot] = fa.y;
            b2[slot] = fb.x; b3[slot] = fb.y; b4v[slot] = fu;
            int goy = oy0 + r0 + i;
            if (gox < VALID && goy < VALID) {
                float ux = t0 * inv, uy = t1 * inv;
                float vx  = cov * (t2 * inv - ux * ux);
                float vy  = cov * (t3 * inv - uy * uy);
                float vxy = cov * (t4 * inv - ux * uy);
                float A1 = 2.f * ux * uy + C1;
                float A2 = 2.f * vxy + C2;
                float B1 = ux * ux + uy * uy + C1;
                float B2 = vx + vy + C2;
                lsum += __fdividef(A1 * A2, B1 * B2);
            }
        }
    }

    // ---- Block reduce (sa, sq, lsum) -> partial stores ----
#pragma unroll
    for (int o = 16; o; o >>= 1) {
        sa += __shfl_down_sync(F, sa, o);
        sq += __shfl_down_sync(F, sq, o);
        lsum += __shfl_down_sync(F, lsum, o);
    }
    __syncthreads();
    if (lane == 0) { scr[warp] = sa; scr[8 + warp] = sq; scr[16 + warp] = lsum; }
    __syncthreads();
    __shared__ bool is_last;
    if (tid == 0) {
        float A = 0.f, Q = 0.f, S = 0.f;
#pragma unroll
        for (int i = 0; i < 8; i++) { A += scr[i]; Q += scr[8 + i]; S += scr[16 + i]; }
        int bid = blockIdx.x + (blockIdx.y << 3) + (blockIdx.z << 7);
        g_pabs[bid] = A;
        g_psq[bid] = Q;
        g_pS[bid] = S;
        __threadfence();
        unsigned old = atomicAdd(&g_count, 1u);
        is_last = (old == NBLK - 1);
    }
    __syncthreads();

    // ---- Last block: reduce all partials, write outputs, reset counter ----
    if (is_last) {
        double a = 0.0, q = 0.0, s = 0.0;
        for (int i = tid; i < NBLK; i += 256) {
            a += (double)g_pabs[i];
            q += (double)g_psq[i];
            s += (double)g_pS[i];
        }
#pragma unroll
        for (int o = 16; o; o >>= 1) {
            a += __shfl_down_sync(F, a, o);
            q += __shfl_down_sync(F, q, o);
            s += __shfl_down_sync(F, s, o);
        }
        if (lane == 0) { dred[warp] = a; dred[8 + warp] = q; dred[16 + warp] = s; }
        __syncthreads();
        if (tid == 0) {
            double A = 0.0, Q = 0.0, S = 0.0;
#pragma unroll
            for (int i = 0; i < 8; i++) {
                A += dred[i]; Q += dred[8 + i]; S += dred[16 + i];
            }
            double mae = A / N_TOTAL;
            double mse = Q / N_TOTAL;
            double ssim_loss = 1.0 - S / N_SSIM;
            double total = mae + 0.5 * mse + 0.2 * ssim_loss;
            out[0] = (float)total;
            out[1] = (float)mae;
            out[2] = (float)mse;
            out[3] = (float)ssim_loss;
            g_count = 0;                 // reset for next graph replay
        }
    }
}

// ---------------------------------------------------------------------------
extern "C" void kernel_launch(void* const* d_in, const int* in_sizes, int n_in,
                              void* d_out, int out_size)
{
    const float* y_pred = (const float*)d_in[0];
    const float* y_true = (const float*)d_in[1];
    const float* mask   = (const float*)d_in[2];
    float* out = (float*)d_out;

    cudaFuncSetAttribute(k_ssim, cudaFuncAttributeMaxDynamicSharedMemorySize,
                         SMEM_BYTES);

    k_range<<<IMGS * RB, 256>>>((const float4*)y_true, (const float4*)mask);
    dim3 grid(GRID_X, GRID_Y, IMGS);
    k_ssim<<<grid, 256, SMEM_BYTES>>>(y_pred, y_true, mask, out);
}